// round 1
// baseline (speedup 1.0000x reference)
#include <cuda_runtime.h>
#include <cuda_bf16.h>
#include <math.h>

#define LL 2
#define BB 2
#define SS 1024
#define DD 1024
#define HH 16
#define HDD 64
#define FFD 4096
#define VV 32000
#define RR 16
#define MM (BB*SS)          // 2048 rows
#define LORA_SCALE 2.0f
#define EPSV 1e-6f

// ---------------- scratch (static device, no allocation) ----------------
__device__ float g_x [MM*DD];
__device__ float g_dx[MM*DD];
__device__ float g_h [MM*DD];
__device__ float g_dh[MM*DD];
__device__ float g_q [MM*DD];
__device__ float g_k [MM*DD];
__device__ float g_v [MM*DD];
__device__ float g_dq[MM*DD];
__device__ float g_dk[MM*DD];
__device__ float g_dv[MM*DD];
__device__ float g_o [MM*DD];
__device__ float g_do[MM*DD];
__device__ float g_t [MM*RR];
__device__ float g_p [BB*HH*SS*SS];   // scores -> probs
__device__ float g_dp[BB*HH*SS*SS];   // dscores -> dprobs
__device__ float g_u [MM*FFD];
__device__ float g_du[MM*FFD];

// ---------------- helpers ----------------
__device__ __forceinline__ float blk_sum(float v, float* sm) {
    int tid = threadIdx.x;
    sm[tid] = v; __syncthreads();
    for (int s = 128; s > 0; s >>= 1) { if (tid < s) sm[tid] += sm[tid + s]; __syncthreads(); }
    float r = sm[0]; __syncthreads(); return r;
}
__device__ __forceinline__ float blk_max(float v, float* sm) {
    int tid = threadIdx.x;
    sm[tid] = v; __syncthreads();
    for (int s = 128; s > 0; s >>= 1) { if (tid < s) sm[tid] = fmaxf(sm[tid], sm[tid + s]); __syncthreads(); }
    float r = sm[0]; __syncthreads(); return r;
}

// ---------------- embed gather + zero tangent ----------------
__global__ void embed_kernel(const int* __restrict__ ids, const float* __restrict__ emb,
                             float* __restrict__ x, float* __restrict__ dx) {
    long i = (long)blockIdx.x * blockDim.x + threadIdx.x;
    int col = (int)(i % DD);
    int row = (int)(i / DD);
    x[i]  = emb[(long)ids[row] * DD + col];
    dx[i] = 0.f;
}

// ---------------- RMSNorm JVP (block per row) ----------------
__global__ void rms_jvp_kernel(const float* __restrict__ x, const float* __restrict__ dx,
                               const float* __restrict__ g,
                               float* __restrict__ h, float* __restrict__ dh) {
    __shared__ float sm[256];
    int row = blockIdx.x;
    const float* xr  = x  + (long)row * DD;
    const float* dxr = dx + (long)row * DD;
    float*       hr  = h  + (long)row * DD;
    float*       dhr = dh + (long)row * DD;
    int tid = threadIdx.x;
    float s2 = 0.f, sxd = 0.f;
    for (int i = tid; i < DD; i += 256) { float xv = xr[i], dv = dxr[i]; s2 += xv*xv; sxd += xv*dv; }
    s2  = blk_sum(s2,  sm);
    sxd = blk_sum(sxd, sm);
    float m = s2 / (float)DD;
    float r = rsqrtf(m + EPSV);
    float c = (sxd / (float)DD) * r * r * r;
    for (int i = tid; i < DD; i += 256) {
        float xv = xr[i], dv = dxr[i], gv = g[i];
        hr[i]  = xv * gv * r;
        dhr[i] = gv * (dv * r - xv * c);
    }
}

// ---------------- GELU (tanh) JVP, in-place ----------------
__global__ void gelu_jvp_kernel(float* __restrict__ u, float* __restrict__ du) {
    long i = (long)blockIdx.x * blockDim.x + threadIdx.x;
    float x = u[i], d = du[i];
    const float c0 = 0.7978845608028654f, c1 = 0.044715f;
    float x2 = x * x;
    float t  = tanhf(c0 * (x + c1 * x * x2));
    float gl = 0.5f * x * (1.f + t);
    float dg = 0.5f * (1.f + t) + 0.5f * x * (1.f - t*t) * c0 * (1.f + 3.f * c1 * x2);
    u[i]  = gl;
    du[i] = dg * d;
}

// ---------------- causal softmax JVP, in-place (block per row) ----------------
__global__ void softmax_jvp_kernel(float* __restrict__ p, float* __restrict__ dp) {
    __shared__ float sm[256];
    long row = blockIdx.x;                   // 0 .. B*H*S-1
    int qpos = (int)(row % SS);
    int nvalid = qpos + 1;
    float* pr  = p  + row * SS;
    float* dpr = dp + row * SS;
    int tid = threadIdx.x;
    float s[4], ds[4];
    float mx = -1e30f;
    #pragma unroll
    for (int i = 0; i < 4; i++) {
        int kpos = tid + i * 256;
        bool ok = kpos < nvalid;
        s[i]  = ok ? pr[kpos]  : -1e30f;
        ds[i] = ok ? dpr[kpos] : 0.f;
        mx = fmaxf(mx, s[i]);
    }
    mx = blk_max(mx, sm);
    float e[4]; float sum = 0.f, dot = 0.f;
    #pragma unroll
    for (int i = 0; i < 4; i++) {
        int kpos = tid + i * 256;
        e[i] = (kpos < nvalid) ? expf(s[i] - mx) : 0.f;
        sum += e[i];
        dot += e[i] * ds[i];
    }
    sum = blk_sum(sum, sm);
    dot = blk_sum(dot, sm);
    float inv = 1.f / sum;
    float pd  = dot * inv;
    #pragma unroll
    for (int i = 0; i < 4; i++) {
        int kpos = tid + i * 256;
        float pv = e[i] * inv;
        pr[kpos]  = pv;
        dpr[kpos] = pv * (ds[i] - pd);
    }
}

// ---------------- add: a += b ----------------
__global__ void add_kernel(float* __restrict__ a, const float* __restrict__ b) {
    long i = (long)blockIdx.x * blockDim.x + threadIdx.x;
    a[i] += b[i];
}

// ---------------- generic tiled GEMM ----------------
// C = alpha * A*op(B) + beta*C, batched via z with two-level offsets.
#define BM 64
#define BN 64
#define BK 16
template<bool TB>
__global__ void gemm_kernel(const float* __restrict__ A, const float* __restrict__ B,
                            float* __restrict__ C, int M, int N, int K,
                            int lda, int ldb, int ldc,
                            float alpha, float beta, int bdiv,
                            long as1, long as2, long bs1, long bs2, long cs1, long cs2) {
    int z = blockIdx.z;
    A += (long)(z / bdiv) * as1 + (long)(z % bdiv) * as2;
    B += (long)(z / bdiv) * bs1 + (long)(z % bdiv) * bs2;
    C += (long)(z / bdiv) * cs1 + (long)(z % bdiv) * cs2;
    __shared__ float As[BK][BM + 1];
    __shared__ float Bs[BK][BN + 1];
    int tid = threadIdx.x;
    int tx = tid % 16, ty = tid / 16;
    int m0 = blockIdx.y * BM, n0 = blockIdx.x * BN;
    float acc[4][4] = {};
    for (int k0 = 0; k0 < K; k0 += BK) {
        {   // A tile: 64 rows x 16 k
            int kk = tid % 16; int mrel = tid / 16;
            #pragma unroll
            for (int i = 0; i < 4; i++) {
                int m = mrel + i * 16;
                int gm = m0 + m;
                As[kk][m] = (gm < M) ? A[(long)gm * lda + k0 + kk] : 0.f;
            }
        }
        if (!TB) {  // B tile: 16 k x 64 n
            int n = tid % 64; int kk0 = tid / 64;
            #pragma unroll
            for (int i = 0; i < 4; i++) {
                int kk = kk0 + i * 4;
                int gn = n0 + n;
                Bs[kk][n] = (gn < N) ? B[(long)(k0 + kk) * ldb + gn] : 0.f;
            }
        } else {    // B is [N,K]: load transposed
            int kk = tid % 16; int nrel = tid / 16;
            #pragma unroll
            for (int i = 0; i < 4; i++) {
                int n = nrel + i * 16;
                int gn = n0 + n;
                Bs[kk][n] = (gn < N) ? B[(long)gn * ldb + k0 + kk] : 0.f;
            }
        }
        __syncthreads();
        #pragma unroll
        for (int kk = 0; kk < BK; kk++) {
            float ra[4], rb[4];
            #pragma unroll
            for (int i = 0; i < 4; i++) ra[i] = As[kk][ty + 16 * i];
            #pragma unroll
            for (int j = 0; j < 4; j++) rb[j] = Bs[kk][tx + 16 * j];
            #pragma unroll
            for (int i = 0; i < 4; i++)
                #pragma unroll
                for (int j = 0; j < 4; j++)
                    acc[i][j] += ra[i] * rb[j];
        }
        __syncthreads();
    }
    #pragma unroll
    for (int i = 0; i < 4; i++) {
        int gm = m0 + ty + 16 * i;
        if (gm >= M) continue;
        #pragma unroll
        for (int j = 0; j < 4; j++) {
            int gn = n0 + tx + 16 * j;
            if (gn >= N) continue;
            long idx = (long)gm * ldc + gn;
            float prev = (beta != 0.f) ? beta * C[idx] : 0.f;
            C[idx] = alpha * acc[i][j] + prev;
        }
    }
}

// ---------------- host side ----------------
static void gemm(const float* A, const float* B, float* C,
                 int M, int N, int K, int lda, int ldb, int ldc,
                 float alpha, float beta, bool tb,
                 int batch = 1, int bdiv = 1,
                 long as1 = 0, long as2 = 0, long bs1 = 0, long bs2 = 0,
                 long cs1 = 0, long cs2 = 0) {
    dim3 grid((N + BN - 1) / BN, (M + BM - 1) / BM, batch);
    if (tb)
        gemm_kernel<true><<<grid, 256>>>(A, B, C, M, N, K, lda, ldb, ldc, alpha, beta,
                                         bdiv, as1, as2, bs1, bs2, cs1, cs2);
    else
        gemm_kernel<false><<<grid, 256>>>(A, B, C, M, N, K, lda, ldb, ldc, alpha, beta,
                                          bdiv, as1, as2, bs1, bs2, cs1, cs2);
}

extern "C" void kernel_launch(void* const* d_in, const int* in_sizes, int n_in,
                              void* d_out, int out_size) {
    const int*   ids    = (const int*)  d_in[0];
    const float* emb    = (const float*)d_in[1];
    const float* Wq     = (const float*)d_in[2];
    const float* Wk     = (const float*)d_in[3];
    const float* Wv     = (const float*)d_in[4];
    const float* Wo     = (const float*)d_in[5];
    const float* W1     = (const float*)d_in[6];
    const float* W2     = (const float*)d_in[7];
    const float* ln1    = (const float*)d_in[8];
    const float* ln2    = (const float*)d_in[9];
    const float* lnf    = (const float*)d_in[10];
    const float* lmh    = (const float*)d_in[11];
    const float* Aq0    = (const float*)d_in[12];
    // d_in[13] = Bq0 (zero), d_in[15] = Bv0 (zero) -- unused by the math
    const float* Av0    = (const float*)d_in[14];
    const float* Bq     = (const float*)d_in[17];
    const float* Bv     = (const float*)d_in[19];
    float* out = (float*)d_out;

    float *x, *dx, *h, *dh, *q, *k_, *v, *dq, *dk, *dv, *o, *do_, *t, *p, *dp, *u, *du;
    cudaGetSymbolAddress((void**)&x,  g_x);
    cudaGetSymbolAddress((void**)&dx, g_dx);
    cudaGetSymbolAddress((void**)&h,  g_h);
    cudaGetSymbolAddress((void**)&dh, g_dh);
    cudaGetSymbolAddress((void**)&q,  g_q);
    cudaGetSymbolAddress((void**)&k_, g_k);
    cudaGetSymbolAddress((void**)&v,  g_v);
    cudaGetSymbolAddress((void**)&dq, g_dq);
    cudaGetSymbolAddress((void**)&dk, g_dk);
    cudaGetSymbolAddress((void**)&dv, g_dv);
    cudaGetSymbolAddress((void**)&o,  g_o);
    cudaGetSymbolAddress((void**)&do_, g_do);
    cudaGetSymbolAddress((void**)&t,  g_t);
    cudaGetSymbolAddress((void**)&p,  g_p);
    cudaGetSymbolAddress((void**)&dp, g_dp);
    cudaGetSymbolAddress((void**)&u,  g_u);
    cudaGetSymbolAddress((void**)&du, g_du);

    const long SD  = (long)SS * DD;     // per-batch stride in q/k/v
    const long HSS = (long)HH * SS * SS;
    const long S2  = (long)SS * SS;
    const float scale = 1.f / 8.f;      // 1/sqrt(64)

    embed_kernel<<<(MM * DD) / 256, 256>>>(ids, emb, x, dx);

    for (int l = 0; l < LL; l++) {
        const float* Wql  = Wq  + (long)l * DD * DD;
        const float* Wkl  = Wk  + (long)l * DD * DD;
        const float* Wvl  = Wv  + (long)l * DD * DD;
        const float* Wol  = Wo  + (long)l * DD * DD;
        const float* W1l  = W1  + (long)l * DD * FFD;
        const float* W2l  = W2  + (long)l * FFD * DD;
        const float* Aq0l = Aq0 + (long)l * RR * DD;
        const float* Av0l = Av0 + (long)l * RR * DD;
        const float* Bql  = Bq  + (long)l * DD * RR;
        const float* Bvl  = Bv  + (long)l * DD * RR;

        rms_jvp_kernel<<<MM, 256>>>(x, dx, ln1 + (long)l * DD, h, dh);

        // primal projections (LoRA contributes 0 since B0 = 0)
        gemm(h,  Wql, q,  MM, DD, DD, DD, DD, DD, 1.f, 0.f, false);
        gemm(h,  Wkl, k_, MM, DD, DD, DD, DD, DD, 1.f, 0.f, false);
        gemm(h,  Wvl, v,  MM, DD, DD, DD, DD, DD, 1.f, 0.f, false);
        // tangent projections
        gemm(dh, Wql, dq, MM, DD, DD, DD, DD, DD, 1.f, 0.f, false);
        gemm(dh, Wkl, dk, MM, DD, DD, DD, DD, DD, 1.f, 0.f, false);
        gemm(dh, Wvl, dv, MM, DD, DD, DD, DD, DD, 1.f, 0.f, false);
        // LoRA tangent: dq += scale * (h @ Aq0^T) @ Bq^T
        gemm(h, Aq0l, t,  MM, RR, DD, DD, DD, RR, 1.f, 0.f, true);
        gemm(t, Bql,  dq, MM, DD, RR, RR, RR, DD, LORA_SCALE, 1.f, true);
        // LoRA tangent: dv += scale * (h @ Av0^T) @ Bv^T
        gemm(h, Av0l, t,  MM, RR, DD, DD, DD, RR, 1.f, 0.f, true);
        gemm(t, Bvl,  dv, MM, DD, RR, RR, RR, DD, LORA_SCALE, 1.f, true);

        // attention scores (batched over B*H)
        gemm(q,  k_, p,  SS, SS, HDD, DD, DD, SS, scale, 0.f, true,
             BB * HH, HH, SD, HDD, SD, HDD, HSS, S2);
        gemm(dq, k_, dp, SS, SS, HDD, DD, DD, SS, scale, 0.f, true,
             BB * HH, HH, SD, HDD, SD, HDD, HSS, S2);
        gemm(q,  dk, dp, SS, SS, HDD, DD, DD, SS, scale, 1.f, true,
             BB * HH, HH, SD, HDD, SD, HDD, HSS, S2);

        softmax_jvp_kernel<<<BB * HH * SS, 256>>>(p, dp);

        // o = p v ; do = dp v + p dv
        gemm(p,  v,  o,  SS, HDD, SS, SS, DD, DD, 1.f, 0.f, false,
             BB * HH, HH, HSS, S2, SD, HDD, SD, HDD);
        gemm(dp, v,  do_, SS, HDD, SS, SS, DD, DD, 1.f, 0.f, false,
             BB * HH, HH, HSS, S2, SD, HDD, SD, HDD);
        gemm(p,  dv, do_, SS, HDD, SS, SS, DD, DD, 1.f, 1.f, false,
             BB * HH, HH, HSS, S2, SD, HDD, SD, HDD);

        // residual
        gemm(o,   Wol, x,  MM, DD, DD, DD, DD, DD, 1.f, 1.f, false);
        gemm(do_, Wol, dx, MM, DD, DD, DD, DD, DD, 1.f, 1.f, false);

        // FFN
        rms_jvp_kernel<<<MM, 256>>>(x, dx, ln2 + (long)l * DD, h, dh);
        gemm(h,  W1l, u,  MM, FFD, DD, DD, FFD, FFD, 1.f, 0.f, false);
        gemm(dh, W1l, du, MM, FFD, DD, DD, FFD, FFD, 1.f, 0.f, false);
        gelu_jvp_kernel<<<(MM * FFD) / 256, 256>>>(u, du);
        gemm(u,  W2l, x,  MM, DD, FFD, FFD, DD, DD, 1.f, 1.f, false);
        gemm(du, W2l, dx, MM, DD, FFD, FFD, DD, DD, 1.f, 1.f, false);
    }

    // final norm + combine + lm head
    rms_jvp_kernel<<<MM, 256>>>(x, dx, lnf, h, dh);
    add_kernel<<<(MM * DD) / 256, 256>>>(h, dh);
    gemm(h, lmh, out, MM, VV, DD, DD, VV, VV, 1.f, 0.f, false);
}

// round 2
// speedup vs baseline: 4.0881x; 4.0881x over previous
#include <cuda_runtime.h>
#include <cuda_bf16.h>
#include <math.h>
#include <stdint.h>

#define LL 2
#define BB 2
#define SS 1024
#define DD 1024
#define HH 16
#define HDD 64
#define FFD 4096
#define VV 32000
#define RR 16
#define MM (BB*SS)          // 2048 rows
#define LORA_SCALE 2.0f
#define EPSV 1e-6f

// ---------------- scratch (static device, no allocation) ----------------
// Primal/tangent pairs stored contiguously: [2][MM][*]
__device__ float g_x2  [2L*MM*DD];
__device__ float g_h2  [2L*MM*DD];
__device__ float g_qkv2[2L*MM*3*DD];
__device__ float g_o2  [2L*MM*DD];
__device__ float g_u2  [2L*MM*FFD];
__device__ float g_p2  [2L*BB*HH*SS*SS];
__device__ float g_t   [MM*RR];
__device__ float g_wcat[DD*3*DD];

// ---------------- helpers ----------------
__device__ __forceinline__ float blk_sum(float v, float* sm) {
    int tid = threadIdx.x;
    sm[tid] = v; __syncthreads();
    for (int s = 128; s > 0; s >>= 1) { if (tid < s) sm[tid] += sm[tid + s]; __syncthreads(); }
    float r = sm[0]; __syncthreads(); return r;
}
__device__ __forceinline__ float blk_max(float v, float* sm) {
    int tid = threadIdx.x;
    sm[tid] = v; __syncthreads();
    for (int s = 128; s > 0; s >>= 1) { if (tid < s) sm[tid] = fmaxf(sm[tid], sm[tid + s]); __syncthreads(); }
    float r = sm[0]; __syncthreads(); return r;
}
__device__ __forceinline__ float to_tf32(float x) {
    uint32_t u; asm("cvt.rna.tf32.f32 %0, %1;" : "=r"(u) : "f"(x));
    return __uint_as_float(u);
}

// ---------------- embed gather + zero tangent ----------------
__global__ void embed_kernel(const int* __restrict__ ids, const float* __restrict__ emb,
                             float* __restrict__ x, float* __restrict__ dx) {
    long i = (long)blockIdx.x * blockDim.x + threadIdx.x;
    int col = (int)(i % DD);
    int row = (int)(i / DD);
    x[i]  = emb[(long)ids[row] * DD + col];
    dx[i] = 0.f;
}

// ---------------- concat Wq|Wk|Wv ----------------
__global__ void catw_kernel(const float* __restrict__ Wq, const float* __restrict__ Wk,
                            const float* __restrict__ Wv, float* __restrict__ out) {
    long i = (long)blockIdx.x * blockDim.x + threadIdx.x;   // over DD*DD
    int d = (int)(i / DD), j = (int)(i % DD);
    out[(long)d * 3*DD + j]        = Wq[i];
    out[(long)d * 3*DD + DD + j]   = Wk[i];
    out[(long)d * 3*DD + 2*DD + j] = Wv[i];
}

// ---------------- RMSNorm JVP (block per row) ----------------
__global__ void rms_jvp_kernel(const float* __restrict__ x, const float* __restrict__ dx,
                               const float* __restrict__ g,
                               float* __restrict__ h, float* __restrict__ dh) {
    __shared__ float sm[256];
    int row = blockIdx.x;
    const float* xr  = x  + (long)row * DD;
    const float* dxr = dx + (long)row * DD;
    float*       hr  = h  + (long)row * DD;
    float*       dhr = dh + (long)row * DD;
    int tid = threadIdx.x;
    float s2 = 0.f, sxd = 0.f;
    for (int i = tid; i < DD; i += 256) { float xv = xr[i], dv = dxr[i]; s2 += xv*xv; sxd += xv*dv; }
    s2  = blk_sum(s2,  sm);
    sxd = blk_sum(sxd, sm);
    float m = s2 / (float)DD;
    float r = rsqrtf(m + EPSV);
    float c = (sxd / (float)DD) * r * r * r;
    for (int i = tid; i < DD; i += 256) {
        float xv = xr[i], dv = dxr[i], gv = g[i];
        hr[i]  = xv * gv * r;
        dhr[i] = gv * (dv * r - xv * c);
    }
}

// ---------------- GELU (tanh) JVP, in-place ----------------
__global__ void gelu_jvp_kernel(float* __restrict__ u, float* __restrict__ du) {
    long i = (long)blockIdx.x * blockDim.x + threadIdx.x;
    float x = u[i], d = du[i];
    const float c0 = 0.7978845608028654f, c1 = 0.044715f;
    float x2 = x * x;
    float t  = tanhf(c0 * (x + c1 * x * x2));
    float gl = 0.5f * x * (1.f + t);
    float dg = 0.5f * (1.f + t) + 0.5f * x * (1.f - t*t) * c0 * (1.f + 3.f * c1 * x2);
    u[i]  = gl;
    du[i] = dg * d;
}

// ---------------- causal softmax JVP, in-place (block per row) ----------------
__global__ void softmax_jvp_kernel(float* __restrict__ p, float* __restrict__ dp) {
    __shared__ float sm[256];
    long row = blockIdx.x;                   // 0 .. B*H*S-1
    int qpos = (int)(row % SS);
    int nvalid = qpos + 1;
    float* pr  = p  + row * SS;
    float* dpr = dp + row * SS;
    int tid = threadIdx.x;
    float s[4], ds[4];
    float mx = -1e30f;
    #pragma unroll
    for (int i = 0; i < 4; i++) {
        int kpos = tid + i * 256;
        bool ok = kpos < nvalid;
        s[i]  = ok ? pr[kpos]  : -1e30f;
        ds[i] = ok ? dpr[kpos] : 0.f;
        mx = fmaxf(mx, s[i]);
    }
    mx = blk_max(mx, sm);
    float e[4]; float sum = 0.f, dot = 0.f;
    #pragma unroll
    for (int i = 0; i < 4; i++) {
        int kpos = tid + i * 256;
        e[i] = (kpos < nvalid) ? expf(s[i] - mx) : 0.f;
        sum += e[i];
        dot += e[i] * ds[i];
    }
    sum = blk_sum(sum, sm);
    dot = blk_sum(dot, sm);
    float inv = 1.f / sum;
    float pd  = dot * inv;
    #pragma unroll
    for (int i = 0; i < 4; i++) {
        int kpos = tid + i * 256;
        float pv = e[i] * inv;
        pr[kpos]  = pv;
        dpr[kpos] = pv * (ds[i] - pd);
    }
}

// ---------------- add: a += b ----------------
__global__ void add_kernel(float* __restrict__ a, const float* __restrict__ b) {
    long i = (long)blockIdx.x * blockDim.x + threadIdx.x;
    a[i] += b[i];
}

// ================= TF32 tensor-core GEMM =================
// C = alpha * A * op(B) + beta*C. Tiles 128 x BN_ x 32, 256 threads, 8 warps (2x4).
// 3-level z batching: z = (i0*d1 + i1)*d2 + i2, per-level pointer strides.
// causal: skip blocks fully above the diagonal (scores). kclip: clamp K to m0+128 (PV).
template<int BN_, bool TB>
__global__ __launch_bounds__(256, 2)
void tc_gemm_kernel(const float* __restrict__ Ag, const float* __restrict__ Bg,
                    float* __restrict__ Cg,
                    int M, int N, int K, int lda, int ldb, int ldc,
                    float alpha, float beta, int d1, int d2,
                    long a0, long a1, long a2,
                    long b0, long b1, long b2,
                    long c0, long c1, long c2,
                    int causal, int kclip)
{
    int z = blockIdx.z;
    int i2 = z % d2; int zt = z / d2; int i1 = zt % d1; int i0 = zt / d1;
    const float* A = Ag + (long)i0*a0 + (long)i1*a1 + (long)i2*a2;
    const float* B = Bg + (long)i0*b0 + (long)i1*b1 + (long)i2*b2;
    float*       C = Cg + (long)i0*c0 + (long)i1*c1 + (long)i2*c2;

    int m0 = blockIdx.y * 128;
    int n0 = blockIdx.x * BN_;
    if (causal && n0 >= m0 + 128) return;
    int Kend = K;
    if (kclip && m0 + 128 < Kend) Kend = m0 + 128;

    constexpr int LDA_S = 36;                          // [m][k] pad 4
    constexpr int LDB_S = TB ? 36 : (BN_ + 8);         // [n][k] pad 4  /  [k][n] pad 8
    __shared__ float As[128 * LDA_S];
    __shared__ float Bs[TB ? (BN_ * 36) : (32 * (BN_ + 8))];

    int tid = threadIdx.x;
    int lane = tid & 31, wid = tid >> 5;
    int wm = wid >> 2, wn = wid & 3;                   // 2 x 4 warp grid
    constexpr int WNW = BN_ / 4;                       // warp n-width: 32 or 16
    constexpr int WNT = WNW / 8;                       // n-tiles: 4 or 2
    int r = lane >> 2, cq = lane & 3;

    float acc[4][WNT][4];
    #pragma unroll
    for (int a = 0; a < 4; a++)
        #pragma unroll
        for (int b = 0; b < WNT; b++)
            #pragma unroll
            for (int c = 0; c < 4; c++) acc[a][b][c] = 0.f;

    for (int k0 = 0; k0 < Kend; k0 += 32) {
        // ---- load A tile [128][32] into [m][k] smem, float4 along k ----
        {
            int kk4 = tid & 7;        // 0..7 (float4 col)
            int mr  = tid >> 3;       // 0..31
            #pragma unroll
            for (int i = 0; i < 4; i++) {
                int m = mr + i * 32;
                int gm = m0 + m;
                float4 av = make_float4(0.f, 0.f, 0.f, 0.f);
                if (gm < M) av = *(const float4*)(A + (long)gm * lda + k0 + kk4 * 4);
                float4 tv = make_float4(to_tf32(av.x), to_tf32(av.y), to_tf32(av.z), to_tf32(av.w));
                *(float4*)&As[m * LDA_S + kk4 * 4] = tv;
            }
        }
        // ---- load B tile ----
        if (TB) {   // B is [N,K] row-major -> smem [n][k]
            int kk4 = tid & 7;
            int nr  = tid >> 3;       // 0..31
            #pragma unroll
            for (int i = 0; i < BN_ / 32; i++) {
                int n = nr + i * 32;
                int gn = n0 + n;
                float4 bv = make_float4(0.f, 0.f, 0.f, 0.f);
                if (gn < N) bv = *(const float4*)(B + (long)gn * ldb + k0 + kk4 * 4);
                float4 tv = make_float4(to_tf32(bv.x), to_tf32(bv.y), to_tf32(bv.z), to_tf32(bv.w));
                *(float4*)&Bs[n * 36 + kk4 * 4] = tv;
            }
        } else {    // B is [K,N] row-major -> smem [k][n]
            constexpr int NP4 = BN_ / 4;       // 32 or 16 float4 per k-row
            constexpr int KP  = 256 / NP4;     // k rows per pass
            int n4 = tid % NP4;
            int kr = tid / NP4;
            #pragma unroll
            for (int i = 0; i < 32 / KP; i++) {
                int kk = kr + i * KP;
                int gn = n0 + n4 * 4;
                float4 bv = make_float4(0.f, 0.f, 0.f, 0.f);
                if (gn < N) bv = *(const float4*)(B + (long)(k0 + kk) * ldb + gn);
                float4 tv = make_float4(to_tf32(bv.x), to_tf32(bv.y), to_tf32(bv.z), to_tf32(bv.w));
                *(float4*)&Bs[kk * LDB_S + n4 * 4] = tv;
            }
        }
        __syncthreads();

        #pragma unroll
        for (int ks = 0; ks < 32; ks += 8) {
            uint32_t af[4][4], bf[WNT][2];
            #pragma unroll
            for (int mt = 0; mt < 4; mt++) {
                int mb = wm * 64 + mt * 16;
                af[mt][0] = __float_as_uint(As[(mb + r    ) * LDA_S + ks + cq    ]);
                af[mt][1] = __float_as_uint(As[(mb + r + 8) * LDA_S + ks + cq    ]);
                af[mt][2] = __float_as_uint(As[(mb + r    ) * LDA_S + ks + cq + 4]);
                af[mt][3] = __float_as_uint(As[(mb + r + 8) * LDA_S + ks + cq + 4]);
            }
            #pragma unroll
            for (int nt = 0; nt < WNT; nt++) {
                int nb = wn * WNW + nt * 8;
                if (TB) {
                    bf[nt][0] = __float_as_uint(Bs[(nb + r) * 36 + ks + cq    ]);
                    bf[nt][1] = __float_as_uint(Bs[(nb + r) * 36 + ks + cq + 4]);
                } else {
                    bf[nt][0] = __float_as_uint(Bs[(ks + cq    ) * LDB_S + nb + r]);
                    bf[nt][1] = __float_as_uint(Bs[(ks + cq + 4) * LDB_S + nb + r]);
                }
            }
            #pragma unroll
            for (int mt = 0; mt < 4; mt++)
                #pragma unroll
                for (int nt = 0; nt < WNT; nt++) {
                    asm volatile(
                        "mma.sync.aligned.m16n8k8.row.col.f32.tf32.tf32.f32 "
                        "{%0,%1,%2,%3}, {%4,%5,%6,%7}, {%8,%9}, {%0,%1,%2,%3};"
                        : "+f"(acc[mt][nt][0]), "+f"(acc[mt][nt][1]),
                          "+f"(acc[mt][nt][2]), "+f"(acc[mt][nt][3])
                        : "r"(af[mt][0]), "r"(af[mt][1]), "r"(af[mt][2]), "r"(af[mt][3]),
                          "r"(bf[nt][0]), "r"(bf[nt][1]));
                }
        }
        __syncthreads();
    }

    // ---- epilogue ----
    #pragma unroll
    for (int mt = 0; mt < 4; mt++) {
        #pragma unroll
        for (int nt = 0; nt < WNT; nt++) {
            int gm = m0 + wm * 64 + mt * 16 + r;
            int gn = n0 + wn * WNW + nt * 8 + cq * 2;
            if (gn < N) {
                if (gm < M) {
                    long idx = (long)gm * ldc + gn;
                    float v0 = alpha * acc[mt][nt][0];
                    float v1 = alpha * acc[mt][nt][1];
                    if (beta != 0.f) {
                        float2 old = *(float2*)(C + idx);
                        v0 += beta * old.x; v1 += beta * old.y;
                    }
                    *(float2*)(C + idx) = make_float2(v0, v1);
                }
                if (gm + 8 < M) {
                    long idx = (long)(gm + 8) * ldc + gn;
                    float v0 = alpha * acc[mt][nt][2];
                    float v1 = alpha * acc[mt][nt][3];
                    if (beta != 0.f) {
                        float2 old = *(float2*)(C + idx);
                        v0 += beta * old.x; v1 += beta * old.y;
                    }
                    *(float2*)(C + idx) = make_float2(v0, v1);
                }
            }
        }
    }
}

// ---------------- SIMT GEMM (for tiny LoRA shapes) ----------------
#define BM 64
#define BN 64
#define BK 16
template<bool TB>
__global__ void gemm_kernel(const float* __restrict__ A, const float* __restrict__ B,
                            float* __restrict__ C, int M, int N, int K,
                            int lda, int ldb, int ldc,
                            float alpha, float beta) {
    __shared__ float As[BK][BM + 1];
    __shared__ float Bs[BK][BN + 1];
    int tid = threadIdx.x;
    int tx = tid % 16, ty = tid / 16;
    int m0 = blockIdx.y * BM, n0 = blockIdx.x * BN;
    float acc[4][4] = {};
    for (int k0 = 0; k0 < K; k0 += BK) {
        {
            int kk = tid % 16; int mrel = tid / 16;
            #pragma unroll
            for (int i = 0; i < 4; i++) {
                int m = mrel + i * 16;
                int gm = m0 + m;
                As[kk][m] = (gm < M) ? A[(long)gm * lda + k0 + kk] : 0.f;
            }
        }
        if (!TB) {
            int n = tid % 64; int kk0 = tid / 64;
            #pragma unroll
            for (int i = 0; i < 4; i++) {
                int kk = kk0 + i * 4;
                int gn = n0 + n;
                Bs[kk][n] = (gn < N) ? B[(long)(k0 + kk) * ldb + gn] : 0.f;
            }
        } else {
            int kk = tid % 16; int nrel = tid / 16;
            #pragma unroll
            for (int i = 0; i < 4; i++) {
                int n = nrel + i * 16;
                int gn = n0 + n;
                Bs[kk][n] = (gn < N) ? B[(long)gn * ldb + k0 + kk] : 0.f;
            }
        }
        __syncthreads();
        #pragma unroll
        for (int kk = 0; kk < BK; kk++) {
            float ra[4], rb[4];
            #pragma unroll
            for (int i = 0; i < 4; i++) ra[i] = As[kk][ty + 16 * i];
            #pragma unroll
            for (int j = 0; j < 4; j++) rb[j] = Bs[kk][tx + 16 * j];
            #pragma unroll
            for (int i = 0; i < 4; i++)
                #pragma unroll
                for (int j = 0; j < 4; j++)
                    acc[i][j] += ra[i] * rb[j];
        }
        __syncthreads();
    }
    #pragma unroll
    for (int i = 0; i < 4; i++) {
        int gm = m0 + ty + 16 * i;
        if (gm >= M) continue;
        #pragma unroll
        for (int j = 0; j < 4; j++) {
            int gn = n0 + tx + 16 * j;
            if (gn >= N) continue;
            long idx = (long)gm * ldc + gn;
            float prev = (beta != 0.f) ? beta * C[idx] : 0.f;
            C[idx] = alpha * acc[i][j] + prev;
        }
    }
}

// ---------------- host wrappers ----------------
static void sgemm(const float* A, const float* B, float* C,
                  int M, int N, int K, int lda, int ldb, int ldc,
                  float alpha, float beta, bool tb) {
    dim3 grid((N + BN - 1) / BN, (M + BM - 1) / BM, 1);
    if (tb) gemm_kernel<true ><<<grid, 256>>>(A, B, C, M, N, K, lda, ldb, ldc, alpha, beta);
    else    gemm_kernel<false><<<grid, 256>>>(A, B, C, M, N, K, lda, ldb, ldc, alpha, beta);
}

struct BatchDesc {
    int nz = 1, d1 = 1, d2 = 1;
    long a0 = 0, a1 = 0, a2 = 0, b0 = 0, b1 = 0, b2 = 0, c0 = 0, c1 = 0, c2 = 0;
};

static void tgemm(const float* A, const float* B, float* C,
                  int M, int N, int K, int lda, int ldb, int ldc,
                  float alpha, float beta, bool tb, bool bn64,
                  const BatchDesc& bd = BatchDesc(), int causal = 0, int kclip = 0) {
    int bn = bn64 ? 64 : 128;
    dim3 grid((N + bn - 1) / bn, (M + 127) / 128, bd.nz);
    if (!bn64) {
        if (tb) tc_gemm_kernel<128, true ><<<grid, 256>>>(A, B, C, M, N, K, lda, ldb, ldc,
            alpha, beta, bd.d1, bd.d2, bd.a0, bd.a1, bd.a2, bd.b0, bd.b1, bd.b2, bd.c0, bd.c1, bd.c2, causal, kclip);
        else    tc_gemm_kernel<128, false><<<grid, 256>>>(A, B, C, M, N, K, lda, ldb, ldc,
            alpha, beta, bd.d1, bd.d2, bd.a0, bd.a1, bd.a2, bd.b0, bd.b1, bd.b2, bd.c0, bd.c1, bd.c2, causal, kclip);
    } else {
        if (tb) tc_gemm_kernel<64, true ><<<grid, 256>>>(A, B, C, M, N, K, lda, ldb, ldc,
            alpha, beta, bd.d1, bd.d2, bd.a0, bd.a1, bd.a2, bd.b0, bd.b1, bd.b2, bd.c0, bd.c1, bd.c2, causal, kclip);
        else    tc_gemm_kernel<64, false><<<grid, 256>>>(A, B, C, M, N, K, lda, ldb, ldc,
            alpha, beta, bd.d1, bd.d2, bd.a0, bd.a1, bd.a2, bd.b0, bd.b1, bd.b2, bd.c0, bd.c1, bd.c2, causal, kclip);
    }
}

extern "C" void kernel_launch(void* const* d_in, const int* in_sizes, int n_in,
                              void* d_out, int out_size) {
    const int*   ids    = (const int*)  d_in[0];
    const float* emb    = (const float*)d_in[1];
    const float* Wq     = (const float*)d_in[2];
    const float* Wk     = (const float*)d_in[3];
    const float* Wv     = (const float*)d_in[4];
    const float* Wo     = (const float*)d_in[5];
    const float* W1     = (const float*)d_in[6];
    const float* W2     = (const float*)d_in[7];
    const float* ln1    = (const float*)d_in[8];
    const float* ln2    = (const float*)d_in[9];
    const float* lnf    = (const float*)d_in[10];
    const float* lmh    = (const float*)d_in[11];
    const float* Aq0    = (const float*)d_in[12];
    const float* Av0    = (const float*)d_in[14];
    const float* Bq     = (const float*)d_in[17];
    const float* Bv     = (const float*)d_in[19];
    float* out = (float*)d_out;

    float *x2, *h2, *qkv2, *o2, *u2, *p2, *t, *wcat;
    cudaGetSymbolAddress((void**)&x2,   g_x2);
    cudaGetSymbolAddress((void**)&h2,   g_h2);
    cudaGetSymbolAddress((void**)&qkv2, g_qkv2);
    cudaGetSymbolAddress((void**)&o2,   g_o2);
    cudaGetSymbolAddress((void**)&u2,   g_u2);
    cudaGetSymbolAddress((void**)&p2,   g_p2);
    cudaGetSymbolAddress((void**)&t,    g_t);
    cudaGetSymbolAddress((void**)&wcat, g_wcat);

    float* x   = x2;            float* dx = x2 + (long)MM*DD;
    float* h   = h2;            float* dh = h2 + (long)MM*DD;
    float* p   = p2;            float* dp = p2 + (long)BB*HH*SS*SS;
    const long PRJ = (long)MM * 3*DD;         // pair stride in qkv2
    const long S2  = (long)SS * SS;
    const float scale = 1.f / 8.f;            // 1/sqrt(64)

    embed_kernel<<<(MM * DD) / 256, 256>>>(ids, emb, x, dx);

    for (int l = 0; l < LL; l++) {
        const float* Wol  = Wo  + (long)l * DD * DD;
        const float* W1l  = W1  + (long)l * DD * FFD;
        const float* W2l  = W2  + (long)l * FFD * DD;
        const float* Aq0l = Aq0 + (long)l * RR * DD;
        const float* Av0l = Av0 + (long)l * RR * DD;
        const float* Bql  = Bq  + (long)l * DD * RR;
        const float* Bvl  = Bv  + (long)l * DD * RR;

        catw_kernel<<<(DD * DD) / 256, 256>>>(Wq + (long)l*DD*DD, Wk + (long)l*DD*DD,
                                              Wv + (long)l*DD*DD, wcat);

        rms_jvp_kernel<<<2 * MM, 256>>>(x2, x2 + (long)MM*DD - (long)0, ln1 + (long)l * DD, h2, h2);
        // NOTE: rms kernel needs distinct primal/tangent pointers per row-pair; do halves separately:
        // (launch above replaced by the two below)
        rms_jvp_kernel<<<MM, 256>>>(x, dx, ln1 + (long)l * DD, h, dh);

        // fused qkv projection: primal+tangent as M=4096
        tgemm(h2, wcat, qkv2, 2*MM, 3*DD, DD, DD, 3*DD, 3*DD, 1.f, 0.f, false, false);

        // LoRA tangent additions (tiny, SIMT)
        sgemm(h, Aq0l, t, MM, RR, DD, DD, DD, RR, 1.f, 0.f, true);
        sgemm(t, Bql, qkv2 + PRJ,          MM, DD, RR, RR, RR, 3*DD, LORA_SCALE, 1.f, true);
        sgemm(h, Av0l, t, MM, RR, DD, DD, DD, RR, 1.f, 0.f, true);
        sgemm(t, Bvl, qkv2 + PRJ + 2*DD,   MM, DD, RR, RR, RR, 3*DD, LORA_SCALE, 1.f, true);

        // scores: pair-merged  {p = q k^T, dp = dq k^T} then dp += q dk^T
        {
            BatchDesc bd; bd.nz = 2*BB*HH; bd.d1 = BB; bd.d2 = HH;
            bd.a0 = PRJ;  bd.a1 = (long)SS*3*DD; bd.a2 = HDD;
            bd.b0 = 0;    bd.b1 = (long)SS*3*DD; bd.b2 = HDD;
            bd.c0 = (long)BB*HH*S2; bd.c1 = (long)HH*S2; bd.c2 = S2;
            tgemm(qkv2, qkv2 + DD, p2, SS, SS, HDD, 3*DD, 3*DD, SS,
                  scale, 0.f, true, false, bd, 1, 0);
            BatchDesc b3 = bd; b3.nz = BB*HH; b3.a0 = 0; b3.b0 = 0; b3.c0 = 0;
            tgemm(qkv2, qkv2 + PRJ + DD, dp, SS, SS, HDD, 3*DD, 3*DD, SS,
                  scale, 1.f, true, false, b3, 1, 0);
        }

        softmax_jvp_kernel<<<BB * HH * SS, 256>>>(p, dp);

        // PV: pair-merged {o = p v, do = dp v} then do += p dv
        {
            BatchDesc bd; bd.nz = 2*BB*HH; bd.d1 = BB; bd.d2 = HH;
            bd.a0 = (long)BB*HH*S2; bd.a1 = (long)HH*S2; bd.a2 = S2;
            bd.b0 = 0;  bd.b1 = (long)SS*3*DD; bd.b2 = HDD;
            bd.c0 = (long)MM*DD; bd.c1 = (long)SS*DD; bd.c2 = HDD;
            tgemm(p2, qkv2 + 2*DD, o2, SS, HDD, SS, SS, 3*DD, DD,
                  1.f, 0.f, false, true, bd, 0, 1);
            BatchDesc b3 = bd; b3.nz = BB*HH; b3.a0 = 0; b3.b0 = 0; b3.c0 = 0;
            tgemm(p, qkv2 + PRJ + 2*DD, o2 + (long)MM*DD, SS, HDD, SS, SS, 3*DD, DD,
                  1.f, 1.f, false, true, b3, 0, 1);
        }

        // residual: x2 += o2 @ Wo (fused pair, M=4096)
        tgemm(o2, Wol, x2, 2*MM, DD, DD, DD, DD, DD, 1.f, 1.f, false, false);

        // FFN
        rms_jvp_kernel<<<MM, 256>>>(x, dx, ln2 + (long)l * DD, h, dh);
        tgemm(h2, W1l, u2, 2*MM, FFD, DD, DD, FFD, FFD, 1.f, 0.f, false, false);
        gelu_jvp_kernel<<<(MM * FFD) / 256, 256>>>(u2, u2 + (long)MM*FFD);
        tgemm(u2, W2l, x2, 2*MM, DD, FFD, FFD, DD, DD, 1.f, 1.f, false, false);
    }

    // final norm + combine + lm head
    rms_jvp_kernel<<<MM, 256>>>(x, dx, lnf, h, dh);
    add_kernel<<<(MM * DD) / 256, 256>>>(h, dh);
    tgemm(h, lmh, out, MM, VV, DD, DD, VV, VV, 1.f, 0.f, false, false);
}

// round 3
// speedup vs baseline: 4.6913x; 1.1475x over previous
#include <cuda_runtime.h>
#include <cuda_bf16.h>
#include <math.h>
#include <stdint.h>

#define LL 2
#define BB 2
#define SS 1024
#define DD 1024
#define HH 16
#define HDD 64
#define FFD 4096
#define VV 32000
#define RR 16
#define MM (BB*SS)          // 2048 rows
#define LORA_SCALE 2.0f
#define EPSV 1e-6f

// ---------------- scratch (static device, no allocation) ----------------
__device__ float g_x2  [2L*MM*DD];
__device__ float g_h2  [2L*MM*DD];
__device__ float g_qkv2[2L*MM*3*DD];
__device__ float g_o2  [2L*MM*DD];
__device__ float g_u2  [2L*MM*FFD];
__device__ float g_p2  [2L*BB*HH*SS*SS];
__device__ float g_t   [MM*RR];
__device__ float g_wcat[DD*3*DD];

// ---------------- helpers ----------------
__device__ __forceinline__ float blk_sum(float v, float* sm) {
    int tid = threadIdx.x;
    sm[tid] = v; __syncthreads();
    for (int s = 128; s > 0; s >>= 1) { if (tid < s) sm[tid] += sm[tid + s]; __syncthreads(); }
    float r = sm[0]; __syncthreads(); return r;
}
__device__ __forceinline__ float blk_max(float v, float* sm) {
    int tid = threadIdx.x;
    sm[tid] = v; __syncthreads();
    for (int s = 128; s > 0; s >>= 1) { if (tid < s) sm[tid] = fmaxf(sm[tid], sm[tid + s]); __syncthreads(); }
    float r = sm[0]; __syncthreads(); return r;
}
__device__ __forceinline__ uint32_t f2tf(float x) {
    uint32_t u; asm("cvt.rna.tf32.f32 %0, %1;" : "=r"(u) : "f"(x));
    return u;
}
__device__ __forceinline__ void cpa16(float* dst, const float* src) {
    uint32_t d = (uint32_t)__cvta_generic_to_shared(dst);
    asm volatile("cp.async.cg.shared.global [%0], [%1], 16;" :: "r"(d), "l"(src));
}
__device__ __forceinline__ void cpa_commit() {
    asm volatile("cp.async.commit_group;" ::: "memory");
}
__device__ __forceinline__ float fast_tanh(float x) {
    float e = __expf(2.f * x);
    return 1.f - 2.f / (e + 1.f);
}

// ---------------- embed gather + zero tangent ----------------
__global__ void embed_kernel(const int* __restrict__ ids, const float* __restrict__ emb,
                             float* __restrict__ x, float* __restrict__ dx) {
    long i = (long)blockIdx.x * blockDim.x + threadIdx.x;
    int col = (int)(i % DD);
    int row = (int)(i / DD);
    x[i]  = emb[(long)ids[row] * DD + col];
    dx[i] = 0.f;
}

// ---------------- concat Wq|Wk|Wv ----------------
__global__ void catw_kernel(const float* __restrict__ Wq, const float* __restrict__ Wk,
                            const float* __restrict__ Wv, float* __restrict__ out) {
    long i = (long)blockIdx.x * blockDim.x + threadIdx.x;   // over DD*DD
    int d = (int)(i / DD), j = (int)(i % DD);
    out[(long)d * 3*DD + j]        = Wq[i];
    out[(long)d * 3*DD + DD + j]   = Wk[i];
    out[(long)d * 3*DD + 2*DD + j] = Wv[i];
}

// ---------------- RMSNorm JVP (block per row) ----------------
__global__ void rms_jvp_kernel(const float* __restrict__ x, const float* __restrict__ dx,
                               const float* __restrict__ g,
                               float* __restrict__ h, float* __restrict__ dh) {
    __shared__ float sm[256];
    int row = blockIdx.x;
    const float* xr  = x  + (long)row * DD;
    const float* dxr = dx + (long)row * DD;
    float*       hr  = h  + (long)row * DD;
    float*       dhr = dh + (long)row * DD;
    int tid = threadIdx.x;
    float s2 = 0.f, sxd = 0.f;
    for (int i = tid; i < DD; i += 256) { float xv = xr[i], dv = dxr[i]; s2 += xv*xv; sxd += xv*dv; }
    s2  = blk_sum(s2,  sm);
    sxd = blk_sum(sxd, sm);
    float m = s2 / (float)DD;
    float r = rsqrtf(m + EPSV);
    float c = (sxd / (float)DD) * r * r * r;
    for (int i = tid; i < DD; i += 256) {
        float xv = xr[i], dv = dxr[i], gv = g[i];
        hr[i]  = xv * gv * r;
        dhr[i] = gv * (dv * r - xv * c);
    }
}

// ---------------- GELU (tanh) JVP, in-place ----------------
__global__ void gelu_jvp_kernel(float* __restrict__ u, float* __restrict__ du) {
    long i = (long)blockIdx.x * blockDim.x + threadIdx.x;
    float x = u[i], d = du[i];
    const float c0 = 0.7978845608028654f, c1 = 0.044715f;
    float x2 = x * x;
    float t  = fast_tanh(c0 * (x + c1 * x * x2));
    float gl = 0.5f * x * (1.f + t);
    float dg = 0.5f * (1.f + t) + 0.5f * x * (1.f - t*t) * c0 * (1.f + 3.f * c1 * x2);
    u[i]  = gl;
    du[i] = dg * d;
}

// ---------------- causal softmax JVP, in-place (block per row) ----------------
__global__ void softmax_jvp_kernel(float* __restrict__ p, float* __restrict__ dp) {
    __shared__ float sm[256];
    long row = blockIdx.x;                   // 0 .. B*H*S-1
    int qpos = (int)(row % SS);
    int nvalid = qpos + 1;
    int kw = ((qpos >> 7) + 1) << 7;         // write up to 128-rounded boundary
    float* pr  = p  + row * SS;
    float* dpr = dp + row * SS;
    int tid = threadIdx.x;
    float s[4], ds[4];
    float mx = -1e30f;
    #pragma unroll
    for (int i = 0; i < 4; i++) {
        int kpos = tid + i * 256;
        bool ok = kpos < nvalid;
        s[i]  = ok ? pr[kpos]  : -1e30f;
        ds[i] = ok ? dpr[kpos] : 0.f;
        mx = fmaxf(mx, s[i]);
    }
    mx = blk_max(mx, sm);
    float e[4]; float sum = 0.f, dot = 0.f;
    #pragma unroll
    for (int i = 0; i < 4; i++) {
        int kpos = tid + i * 256;
        e[i] = (kpos < nvalid) ? __expf(s[i] - mx) : 0.f;
        sum += e[i];
        dot += e[i] * ds[i];
    }
    sum = blk_sum(sum, sm);
    dot = blk_sum(dot, sm);
    float inv = 1.f / sum;
    float pd  = dot * inv;
    #pragma unroll
    for (int i = 0; i < 4; i++) {
        int kpos = tid + i * 256;
        if (kpos < kw) {
            float pv = e[i] * inv;
            pr[kpos]  = pv;
            dpr[kpos] = pv * (ds[i] - pd);
        }
    }
}

// ---------------- add: a += b ----------------
__global__ void add_kernel(float* __restrict__ a, const float* __restrict__ b) {
    long i = (long)blockIdx.x * blockDim.x + threadIdx.x;
    a[i] += b[i];
}

// ================= TF32 tensor-core GEMM, 3-stage cp.async pipeline =================
// C = alpha * A * op(B) + beta*C. Tile 128 x BN_ x 32, 256 threads (2x4 warps).
// All M, N multiples of 128/BN_, K (and Kend) multiples of 32 -- no bounds checks.
template<int BN_, bool TB>
__global__ __launch_bounds__(256, 2)
void tc_gemm_kernel(const float* __restrict__ Ag, const float* __restrict__ Bg,
                    float* __restrict__ Cg,
                    int M, int N, int K, int lda, int ldb, int ldc,
                    float alpha, float beta, int d1, int d2,
                    long a0, long a1, long a2,
                    long b0, long b1, long b2,
                    long c0, long c1, long c2,
                    int causal, int kclip)
{
    extern __shared__ float smem[];
    constexpr int LDA_S = 36;
    constexpr int LDB_S = TB ? 36 : (BN_ + 8);
    constexpr int ASZ = 128 * LDA_S;
    constexpr int BSZ = TB ? (BN_ * 36) : (32 * (BN_ + 8));
    constexpr int STG = ASZ + BSZ;

    int z = blockIdx.z;
    int i2 = z % d2; int zt = z / d2; int i1 = zt % d1; int i0 = zt / d1;
    const float* A = Ag + (long)i0*a0 + (long)i1*a1 + (long)i2*a2;
    const float* B = Bg + (long)i0*b0 + (long)i1*b1 + (long)i2*b2;
    float*       C = Cg + (long)i0*c0 + (long)i1*c1 + (long)i2*c2;

    int m0 = blockIdx.y * 128;
    int n0 = blockIdx.x * BN_;
    if (causal && n0 >= m0 + 128) return;
    int Kend = K;
    if (kclip && m0 + 128 < Kend) Kend = m0 + 128;
    int nIt = Kend >> 5;

    int tid = threadIdx.x;
    int lane = tid & 31, wid = tid >> 5;
    int wm = wid >> 2, wn = wid & 3;
    constexpr int WNW = BN_ / 4;
    constexpr int WNT = WNW / 8;
    int r = lane >> 2, cq = lane & 3;

    int kk4 = tid & 7, mr = tid >> 3;

    auto LOAD = [&](int kt, int st) {
        float* As = smem + st * STG;
        float* Bs = As + ASZ;
        int k0 = kt * 32;
        #pragma unroll
        for (int i = 0; i < 4; i++) {
            int m = mr + i * 32;
            cpa16(&As[m * LDA_S + kk4 * 4], A + (long)(m0 + m) * lda + k0 + kk4 * 4);
        }
        if (TB) {
            #pragma unroll
            for (int i = 0; i < BN_ / 32; i++) {
                int nn = mr + i * 32;
                cpa16(&Bs[nn * 36 + kk4 * 4], B + (long)(n0 + nn) * ldb + k0 + kk4 * 4);
            }
        } else {
            constexpr int NP4 = BN_ / 4;
            constexpr int KP  = 256 / NP4;
            int n4 = tid % NP4, kr = tid / NP4;
            #pragma unroll
            for (int i = 0; i < 32 / KP; i++) {
                int kk = kr + i * KP;
                cpa16(&Bs[kk * LDB_S + n4 * 4], B + (long)(k0 + kk) * ldb + n0 + n4 * 4);
            }
        }
    };

    float acc[4][WNT][4];
    #pragma unroll
    for (int a = 0; a < 4; a++)
        #pragma unroll
        for (int b = 0; b < WNT; b++)
            #pragma unroll
            for (int c = 0; c < 4; c++) acc[a][b][c] = 0.f;

    LOAD(0, 0); cpa_commit();
    if (nIt > 1) LOAD(1, 1);
    cpa_commit();

    for (int it = 0; it < nIt; ++it) {
        if (it < nIt - 1) asm volatile("cp.async.wait_group 1;" ::: "memory");
        else              asm volatile("cp.async.wait_group 0;" ::: "memory");
        __syncthreads();
        const float* As = smem + (it % 3) * STG;
        const float* Bs = As + ASZ;

        #pragma unroll
        for (int ks = 0; ks < 32; ks += 8) {
            uint32_t af[4][4], bf[WNT][2];
            #pragma unroll
            for (int mt = 0; mt < 4; mt++) {
                int mb = wm * 64 + mt * 16;
                af[mt][0] = f2tf(As[(mb + r    ) * LDA_S + ks + cq    ]);
                af[mt][1] = f2tf(As[(mb + r + 8) * LDA_S + ks + cq    ]);
                af[mt][2] = f2tf(As[(mb + r    ) * LDA_S + ks + cq + 4]);
                af[mt][3] = f2tf(As[(mb + r + 8) * LDA_S + ks + cq + 4]);
            }
            #pragma unroll
            for (int nt = 0; nt < WNT; nt++) {
                int nb = wn * WNW + nt * 8;
                if (TB) {
                    bf[nt][0] = f2tf(Bs[(nb + r) * 36 + ks + cq    ]);
                    bf[nt][1] = f2tf(Bs[(nb + r) * 36 + ks + cq + 4]);
                } else {
                    bf[nt][0] = f2tf(Bs[(ks + cq    ) * LDB_S + nb + r]);
                    bf[nt][1] = f2tf(Bs[(ks + cq + 4) * LDB_S + nb + r]);
                }
            }
            #pragma unroll
            for (int mt = 0; mt < 4; mt++)
                #pragma unroll
                for (int nt = 0; nt < WNT; nt++) {
                    asm volatile(
                        "mma.sync.aligned.m16n8k8.row.col.f32.tf32.tf32.f32 "
                        "{%0,%1,%2,%3}, {%4,%5,%6,%7}, {%8,%9}, {%0,%1,%2,%3};"
                        : "+f"(acc[mt][nt][0]), "+f"(acc[mt][nt][1]),
                          "+f"(acc[mt][nt][2]), "+f"(acc[mt][nt][3])
                        : "r"(af[mt][0]), "r"(af[mt][1]), "r"(af[mt][2]), "r"(af[mt][3]),
                          "r"(bf[nt][0]), "r"(bf[nt][1]));
                }
        }

        if (it + 2 < nIt) { LOAD(it + 2, (it + 2) % 3); cpa_commit(); }
    }

    // ---- epilogue ----
    #pragma unroll
    for (int mt = 0; mt < 4; mt++) {
        #pragma unroll
        for (int nt = 0; nt < WNT; nt++) {
            int gm = m0 + wm * 64 + mt * 16 + r;
            int gn = n0 + wn * WNW + nt * 8 + cq * 2;
            {
                long idx = (long)gm * ldc + gn;
                float v0 = alpha * acc[mt][nt][0];
                float v1 = alpha * acc[mt][nt][1];
                if (beta != 0.f) {
                    float2 old = *(float2*)(C + idx);
                    v0 += beta * old.x; v1 += beta * old.y;
                }
                *(float2*)(C + idx) = make_float2(v0, v1);
            }
            {
                long idx = (long)(gm + 8) * ldc + gn;
                float v0 = alpha * acc[mt][nt][2];
                float v1 = alpha * acc[mt][nt][3];
                if (beta != 0.f) {
                    float2 old = *(float2*)(C + idx);
                    v0 += beta * old.x; v1 += beta * old.y;
                }
                *(float2*)(C + idx) = make_float2(v0, v1);
            }
        }
    }
}

// ---------------- SIMT GEMM (tiny LoRA shapes) ----------------
#define BM 64
#define BN 64
#define BK 16
template<bool TB>
__global__ void gemm_kernel(const float* __restrict__ A, const float* __restrict__ B,
                            float* __restrict__ C, int M, int N, int K,
                            int lda, int ldb, int ldc,
                            float alpha, float beta) {
    __shared__ float As[BK][BM + 1];
    __shared__ float Bs[BK][BN + 1];
    int tid = threadIdx.x;
    int tx = tid % 16, ty = tid / 16;
    int m0 = blockIdx.y * BM, n0 = blockIdx.x * BN;
    float acc[4][4] = {};
    for (int k0 = 0; k0 < K; k0 += BK) {
        {
            int kk = tid % 16; int mrel = tid / 16;
            #pragma unroll
            for (int i = 0; i < 4; i++) {
                int m = mrel + i * 16;
                int gm = m0 + m;
                As[kk][m] = (gm < M) ? A[(long)gm * lda + k0 + kk] : 0.f;
            }
        }
        if (!TB) {
            int n = tid % 64; int kk0 = tid / 64;
            #pragma unroll
            for (int i = 0; i < 4; i++) {
                int kk = kk0 + i * 4;
                int gn = n0 + n;
                Bs[kk][n] = (gn < N) ? B[(long)(k0 + kk) * ldb + gn] : 0.f;
            }
        } else {
            int kk = tid % 16; int nrel = tid / 16;
            #pragma unroll
            for (int i = 0; i < 4; i++) {
                int n = nrel + i * 16;
                int gn = n0 + n;
                Bs[kk][n] = (gn < N) ? B[(long)gn * ldb + k0 + kk] : 0.f;
            }
        }
        __syncthreads();
        #pragma unroll
        for (int kk = 0; kk < BK; kk++) {
            float ra[4], rb[4];
            #pragma unroll
            for (int i = 0; i < 4; i++) ra[i] = As[kk][ty + 16 * i];
            #pragma unroll
            for (int j = 0; j < 4; j++) rb[j] = Bs[kk][tx + 16 * j];
            #pragma unroll
            for (int i = 0; i < 4; i++)
                #pragma unroll
                for (int j = 0; j < 4; j++)
                    acc[i][j] += ra[i] * rb[j];
        }
        __syncthreads();
    }
    #pragma unroll
    for (int i = 0; i < 4; i++) {
        int gm = m0 + ty + 16 * i;
        if (gm >= M) continue;
        #pragma unroll
        for (int j = 0; j < 4; j++) {
            int gn = n0 + tx + 16 * j;
            if (gn >= N) continue;
            long idx = (long)gm * ldc + gn;
            float prev = (beta != 0.f) ? beta * C[idx] : 0.f;
            C[idx] = alpha * acc[i][j] + prev;
        }
    }
}

// ---------------- host wrappers ----------------
static void sgemm(const float* A, const float* B, float* C,
                  int M, int N, int K, int lda, int ldb, int ldc,
                  float alpha, float beta, bool tb) {
    dim3 grid((N + BN - 1) / BN, (M + BM - 1) / BM, 1);
    if (tb) gemm_kernel<true ><<<grid, 256>>>(A, B, C, M, N, K, lda, ldb, ldc, alpha, beta);
    else    gemm_kernel<false><<<grid, 256>>>(A, B, C, M, N, K, lda, ldb, ldc, alpha, beta);
}

struct BatchDesc {
    int nz = 1, d1 = 1, d2 = 1;
    long a0 = 0, a1 = 0, a2 = 0, b0 = 0, b1 = 0, b2 = 0, c0 = 0, c1 = 0, c2 = 0;
};

static int tc_smem_bytes(bool bn64, bool tb) {
    int ASZ = 128 * 36;
    int BSZ;
    if (bn64) BSZ = tb ? 64 * 36 : 32 * 72;
    else      BSZ = tb ? 128 * 36 : 32 * 136;
    return 3 * (ASZ + BSZ) * 4;
}

static void tgemm(const float* A, const float* B, float* C,
                  int M, int N, int K, int lda, int ldb, int ldc,
                  float alpha, float beta, bool tb, bool bn64,
                  const BatchDesc& bd = BatchDesc(), int causal = 0, int kclip = 0) {
    int bn = bn64 ? 64 : 128;
    dim3 grid((N + bn - 1) / bn, (M + 127) / 128, bd.nz);
    int smem = tc_smem_bytes(bn64, tb);
    if (!bn64) {
        if (tb) {
            cudaFuncSetAttribute(tc_gemm_kernel<128, true >, cudaFuncAttributeMaxDynamicSharedMemorySize, smem);
            tc_gemm_kernel<128, true ><<<grid, 256, smem>>>(A, B, C, M, N, K, lda, ldb, ldc,
                alpha, beta, bd.d1, bd.d2, bd.a0, bd.a1, bd.a2, bd.b0, bd.b1, bd.b2, bd.c0, bd.c1, bd.c2, causal, kclip);
        } else {
            cudaFuncSetAttribute(tc_gemm_kernel<128, false>, cudaFuncAttributeMaxDynamicSharedMemorySize, smem);
            tc_gemm_kernel<128, false><<<grid, 256, smem>>>(A, B, C, M, N, K, lda, ldb, ldc,
                alpha, beta, bd.d1, bd.d2, bd.a0, bd.a1, bd.a2, bd.b0, bd.b1, bd.b2, bd.c0, bd.c1, bd.c2, causal, kclip);
        }
    } else {
        if (tb) {
            cudaFuncSetAttribute(tc_gemm_kernel<64, true >, cudaFuncAttributeMaxDynamicSharedMemorySize, smem);
            tc_gemm_kernel<64, true ><<<grid, 256, smem>>>(A, B, C, M, N, K, lda, ldb, ldc,
                alpha, beta, bd.d1, bd.d2, bd.a0, bd.a1, bd.a2, bd.b0, bd.b1, bd.b2, bd.c0, bd.c1, bd.c2, causal, kclip);
        } else {
            cudaFuncSetAttribute(tc_gemm_kernel<64, false>, cudaFuncAttributeMaxDynamicSharedMemorySize, smem);
            tc_gemm_kernel<64, false><<<grid, 256, smem>>>(A, B, C, M, N, K, lda, ldb, ldc,
                alpha, beta, bd.d1, bd.d2, bd.a0, bd.a1, bd.a2, bd.b0, bd.b1, bd.b2, bd.c0, bd.c1, bd.c2, causal, kclip);
        }
    }
}

extern "C" void kernel_launch(void* const* d_in, const int* in_sizes, int n_in,
                              void* d_out, int out_size) {
    const int*   ids    = (const int*)  d_in[0];
    const float* emb    = (const float*)d_in[1];
    const float* Wq     = (const float*)d_in[2];
    const float* Wk     = (const float*)d_in[3];
    const float* Wv     = (const float*)d_in[4];
    const float* Wo     = (const float*)d_in[5];
    const float* W1     = (const float*)d_in[6];
    const float* W2     = (const float*)d_in[7];
    const float* ln1    = (const float*)d_in[8];
    const float* ln2    = (const float*)d_in[9];
    const float* lnf    = (const float*)d_in[10];
    const float* lmh    = (const float*)d_in[11];
    const float* Aq0    = (const float*)d_in[12];
    const float* Av0    = (const float*)d_in[14];
    const float* Bq     = (const float*)d_in[17];
    const float* Bv     = (const float*)d_in[19];
    float* out = (float*)d_out;

    float *x2, *h2, *qkv2, *o2, *u2, *p2, *t, *wcat;
    cudaGetSymbolAddress((void**)&x2,   g_x2);
    cudaGetSymbolAddress((void**)&h2,   g_h2);
    cudaGetSymbolAddress((void**)&qkv2, g_qkv2);
    cudaGetSymbolAddress((void**)&o2,   g_o2);
    cudaGetSymbolAddress((void**)&u2,   g_u2);
    cudaGetSymbolAddress((void**)&p2,   g_p2);
    cudaGetSymbolAddress((void**)&t,    g_t);
    cudaGetSymbolAddress((void**)&wcat, g_wcat);

    float* x   = x2;            float* dx = x2 + (long)MM*DD;
    float* h   = h2;            float* dh = h2 + (long)MM*DD;
    float* p   = p2;            float* dp = p2 + (long)BB*HH*SS*SS;
    const long PRJ = (long)MM * 3*DD;         // pair stride in qkv2
    const long S2  = (long)SS * SS;
    const float scale = 1.f / 8.f;            // 1/sqrt(64)

    embed_kernel<<<(MM * DD) / 256, 256>>>(ids, emb, x, dx);

    for (int l = 0; l < LL; l++) {
        const float* Wol  = Wo  + (long)l * DD * DD;
        const float* W1l  = W1  + (long)l * DD * FFD;
        const float* W2l  = W2  + (long)l * FFD * DD;
        const float* Aq0l = Aq0 + (long)l * RR * DD;
        const float* Av0l = Av0 + (long)l * RR * DD;
        const float* Bql  = Bq  + (long)l * DD * RR;
        const float* Bvl  = Bv  + (long)l * DD * RR;

        catw_kernel<<<(DD * DD) / 256, 256>>>(Wq + (long)l*DD*DD, Wk + (long)l*DD*DD,
                                              Wv + (long)l*DD*DD, wcat);

        rms_jvp_kernel<<<MM, 256>>>(x, dx, ln1 + (long)l * DD, h, dh);

        // fused qkv projection: primal+tangent as M=4096
        tgemm(h2, wcat, qkv2, 2*MM, 3*DD, DD, DD, 3*DD, 3*DD, 1.f, 0.f, false, false);

        // LoRA tangent additions (tiny, SIMT)
        sgemm(h, Aq0l, t, MM, RR, DD, DD, DD, RR, 1.f, 0.f, true);
        sgemm(t, Bql, qkv2 + PRJ,          MM, DD, RR, RR, RR, 3*DD, LORA_SCALE, 1.f, true);
        sgemm(h, Av0l, t, MM, RR, DD, DD, DD, RR, 1.f, 0.f, true);
        sgemm(t, Bvl, qkv2 + PRJ + 2*DD,   MM, DD, RR, RR, RR, 3*DD, LORA_SCALE, 1.f, true);

        // scores: pair-merged {p = q k^T, dp = dq k^T} then dp += q dk^T
        {
            BatchDesc bd; bd.nz = 2*BB*HH; bd.d1 = BB; bd.d2 = HH;
            bd.a0 = PRJ;  bd.a1 = (long)SS*3*DD; bd.a2 = HDD;
            bd.b0 = 0;    bd.b1 = (long)SS*3*DD; bd.b2 = HDD;
            bd.c0 = (long)BB*HH*S2; bd.c1 = (long)HH*S2; bd.c2 = S2;
            tgemm(qkv2, qkv2 + DD, p2, SS, SS, HDD, 3*DD, 3*DD, SS,
                  scale, 0.f, true, false, bd, 1, 0);
            BatchDesc b3 = bd; b3.nz = BB*HH; b3.a0 = 0; b3.b0 = 0; b3.c0 = 0;
            tgemm(qkv2, qkv2 + PRJ + DD, dp, SS, SS, HDD, 3*DD, 3*DD, SS,
                  scale, 1.f, true, false, b3, 1, 0);
        }

        softmax_jvp_kernel<<<BB * HH * SS, 256>>>(p, dp);

        // PV: pair-merged {o = p v, do = dp v} then do += p dv
        {
            BatchDesc bd; bd.nz = 2*BB*HH; bd.d1 = BB; bd.d2 = HH;
            bd.a0 = (long)BB*HH*S2; bd.a1 = (long)HH*S2; bd.a2 = S2;
            bd.b0 = 0;  bd.b1 = (long)SS*3*DD; bd.b2 = HDD;
            bd.c0 = (long)MM*DD; bd.c1 = (long)SS*DD; bd.c2 = HDD;
            tgemm(p2, qkv2 + 2*DD, o2, SS, HDD, SS, SS, 3*DD, DD,
                  1.f, 0.f, false, true, bd, 0, 1);
            BatchDesc b3 = bd; b3.nz = BB*HH; b3.a0 = 0; b3.b0 = 0; b3.c0 = 0;
            tgemm(p, qkv2 + PRJ + 2*DD, o2 + (long)MM*DD, SS, HDD, SS, SS, 3*DD, DD,
                  1.f, 1.f, false, true, b3, 0, 1);
        }

        // residual: x2 += o2 @ Wo (fused pair, M=4096)
        tgemm(o2, Wol, x2, 2*MM, DD, DD, DD, DD, DD, 1.f, 1.f, false, false);

        // FFN
        rms_jvp_kernel<<<MM, 256>>>(x, dx, ln2 + (long)l * DD, h, dh);
        tgemm(h2, W1l, u2, 2*MM, FFD, DD, DD, FFD, FFD, 1.f, 0.f, false, false);
        gelu_jvp_kernel<<<(MM * FFD) / 256, 256>>>(u2, u2 + (long)MM*FFD);
        tgemm(u2, W2l, x2, 2*MM, DD, FFD, FFD, DD, DD, 1.f, 1.f, false, false);
    }

    // final norm + combine + lm head
    rms_jvp_kernel<<<MM, 256>>>(x, dx, lnf, h, dh);
    add_kernel<<<(MM * DD) / 256, 256>>>(h, dh);
    tgemm(h, lmh, out, MM, VV, DD, DD, VV, VV, 1.f, 0.f, false, false);
}

// round 5
// speedup vs baseline: 5.2596x; 1.1212x over previous
#include <cuda_runtime.h>
#include <cuda_bf16.h>
#include <math.h>
#include <stdint.h>

#define LL 2
#define BB 2
#define SS 1024
#define DD 1024
#define HH 16
#define HDD 64
#define FFD 4096
#define VV 32000
#define RR 16
#define MM (BB*SS)          // 2048 rows
#define LORA_SCALE 2.0f
#define EPSV 1e-6f

// ---------------- scratch (static device, no allocation) ----------------
__device__ float g_x2  [2L*MM*DD];
__device__ float g_h2  [2L*MM*DD];
__device__ float g_qkv2[2L*MM*3*DD];
__device__ float g_o2  [2L*MM*DD];
__device__ float g_u2  [2L*MM*FFD];
__device__ float g_p2  [2L*BB*HH*SS*SS];
__device__ float g_t   [MM*RR];
__device__ float g_wcat[DD*3*DD];
__device__ float g_woc [DD*DD];
__device__ float g_w1c [DD*FFD];
__device__ float g_w2c [FFD*DD];
__device__ float g_lmc [DD*VV];

// ---------------- helpers ----------------
__device__ __forceinline__ float blk_sum(float v, float* sm) {
    int tid = threadIdx.x;
    sm[tid] = v; __syncthreads();
    for (int s = 128; s > 0; s >>= 1) { if (tid < s) sm[tid] += sm[tid + s]; __syncthreads(); }
    float r = sm[0]; __syncthreads(); return r;
}
__device__ __forceinline__ float blk_max(float v, float* sm) {
    int tid = threadIdx.x;
    sm[tid] = v; __syncthreads();
    for (int s = 128; s > 0; s >>= 1) { if (tid < s) sm[tid] = fmaxf(sm[tid], sm[tid + s]); __syncthreads(); }
    float r = sm[0]; __syncthreads(); return r;
}
__device__ __forceinline__ float cvtf(float x) {
    uint32_t u; asm("cvt.rna.tf32.f32 %0, %1;" : "=r"(u) : "f"(x));
    return __uint_as_float(u);
}
__device__ __forceinline__ void cpa16(float* dst, const float* src) {
    uint32_t d = (uint32_t)__cvta_generic_to_shared(dst);
    asm volatile("cp.async.cg.shared.global [%0], [%1], 16;" :: "r"(d), "l"(src));
}
__device__ __forceinline__ void cpa_commit() {
    asm volatile("cp.async.commit_group;" ::: "memory");
}
__device__ __forceinline__ float fast_tanh(float x) {
    float e = __expf(2.f * x);
    return 1.f - 2.f / (e + 1.f);
}

// ---------------- embed gather + zero tangent ----------------
__global__ void embed_kernel(const int* __restrict__ ids, const float* __restrict__ emb,
                             float* __restrict__ x, float* __restrict__ dx) {
    long i = (long)blockIdx.x * blockDim.x + threadIdx.x;
    int col = (int)(i % DD);
    int row = (int)(i / DD);
    x[i]  = emb[(long)ids[row] * DD + col];
    dx[i] = 0.f;
}

// ---------------- zero fill ----------------
__global__ void zero_kernel(float* __restrict__ a) {
    long i = (long)blockIdx.x * blockDim.x + threadIdx.x;
    ((float4*)a)[i] = make_float4(0.f, 0.f, 0.f, 0.f);
}

// ---------------- cvt copy (tf32-round) ----------------
__global__ void cvtcopy_kernel(const float* __restrict__ in, float* __restrict__ out) {
    long i = (long)blockIdx.x * blockDim.x + threadIdx.x;
    float4 v = ((const float4*)in)[i];
    ((float4*)out)[i] = make_float4(cvtf(v.x), cvtf(v.y), cvtf(v.z), cvtf(v.w));
}

// ---------------- concat Wq|Wk|Wv with tf32 round ----------------
__global__ void catw_kernel(const float* __restrict__ Wq, const float* __restrict__ Wk,
                            const float* __restrict__ Wv, float* __restrict__ out) {
    long i = (long)blockIdx.x * blockDim.x + threadIdx.x;   // over DD*DD
    int d = (int)(i / DD), j = (int)(i % DD);
    out[(long)d * 3*DD + j]        = cvtf(Wq[i]);
    out[(long)d * 3*DD + DD + j]   = cvtf(Wk[i]);
    out[(long)d * 3*DD + 2*DD + j] = cvtf(Wv[i]);
}

// ---------------- RMSNorm JVP (block per row), tf32-rounded outputs ----------------
__global__ void rms_jvp_kernel(const float* __restrict__ x, const float* __restrict__ dx,
                               const float* __restrict__ g,
                               float* __restrict__ h, float* __restrict__ dh) {
    __shared__ float sm[256];
    int row = blockIdx.x;
    const float* xr  = x  + (long)row * DD;
    const float* dxr = dx + (long)row * DD;
    float*       hr  = h  + (long)row * DD;
    float*       dhr = dh + (long)row * DD;
    int tid = threadIdx.x;
    float s2 = 0.f, sxd = 0.f;
    for (int i = tid; i < DD; i += 256) { float xv = xr[i], dv = dxr[i]; s2 += xv*xv; sxd += xv*dv; }
    s2  = blk_sum(s2,  sm);
    sxd = blk_sum(sxd, sm);
    float m = s2 / (float)DD;
    float r = rsqrtf(m + EPSV);
    float c = (sxd / (float)DD) * r * r * r;
    for (int i = tid; i < DD; i += 256) {
        float xv = xr[i], dv = dxr[i], gv = g[i];
        hr[i]  = cvtf(xv * gv * r);
        dhr[i] = cvtf(gv * (dv * r - xv * c));
    }
}

// ---------------- GELU JVP, in-place, tf32-rounded outputs ----------------
__global__ void gelu_jvp_kernel(float* __restrict__ u, float* __restrict__ du) {
    long i = (long)blockIdx.x * blockDim.x + threadIdx.x;
    float x = u[i], d = du[i];
    const float c0 = 0.7978845608028654f, c1 = 0.044715f;
    float x2 = x * x;
    float t  = fast_tanh(c0 * (x + c1 * x * x2));
    float gl = 0.5f * x * (1.f + t);
    float dg = 0.5f * (1.f + t) + 0.5f * x * (1.f - t*t) * c0 * (1.f + 3.f * c1 * x2);
    u[i]  = cvtf(gl);
    du[i] = cvtf(dg * d);
}

// ---------------- causal softmax JVP, in-place, tf32-rounded ----------------
__global__ void softmax_jvp_kernel(float* __restrict__ p, float* __restrict__ dp) {
    __shared__ float sm[256];
    long row = blockIdx.x;                   // 0 .. B*H*S-1
    int qpos = (int)(row % SS);
    int nvalid = qpos + 1;
    int kw = ((qpos >> 7) + 1) << 7;         // write to 128-rounded boundary
    float* pr  = p  + row * SS;
    float* dpr = dp + row * SS;
    int tid = threadIdx.x;
    float s[4], ds[4];
    float mx = -1e30f;
    #pragma unroll
    for (int i = 0; i < 4; i++) {
        int kpos = tid + i * 256;
        bool ok = kpos < nvalid;
        s[i]  = ok ? pr[kpos]  : -1e30f;
        ds[i] = ok ? dpr[kpos] : 0.f;
        mx = fmaxf(mx, s[i]);
    }
    mx = blk_max(mx, sm);
    float e[4]; float sum = 0.f, dot = 0.f;
    #pragma unroll
    for (int i = 0; i < 4; i++) {
        int kpos = tid + i * 256;
        e[i] = (kpos < nvalid) ? __expf(s[i] - mx) : 0.f;
        sum += e[i];
        dot += e[i] * ds[i];
    }
    sum = blk_sum(sum, sm);
    dot = blk_sum(dot, sm);
    float inv = 1.f / sum;
    float pd  = dot * inv;
    #pragma unroll
    for (int i = 0; i < 4; i++) {
        int kpos = tid + i * 256;
        if (kpos < kw) {
            float pv = e[i] * inv;
            pr[kpos]  = cvtf(pv);
            dpr[kpos] = cvtf(pv * (ds[i] - pd));
        }
    }
}

// ---------------- add: a = cvt(a + b) ----------------
__global__ void add_kernel(float* __restrict__ a, const float* __restrict__ b) {
    long i = (long)blockIdx.x * blockDim.x + threadIdx.x;
    a[i] = cvtf(a[i] + b[i]);
}

// ================= TF32 tensor-core GEMM, 3-stage cp.async pipeline =================
// Inputs are PRE-ROUNDED to tf32 -- mainloop loads raw bits (no CVT).
// CVTO: round outputs to tf32 in epilogue (when C feeds another tc GEMM).
template<int BN_, bool TB, bool CVTO>
__global__ __launch_bounds__(256, 2)
void tc_gemm_kernel(const float* __restrict__ Ag, const float* __restrict__ Bg,
                    float* __restrict__ Cg,
                    int M, int N, int K, int lda, int ldb, int ldc,
                    float alpha, float beta, int d1, int d2,
                    long a0, long a1, long a2,
                    long b0, long b1, long b2,
                    long c0, long c1, long c2,
                    int causal, int kclip)
{
    extern __shared__ float smem[];
    constexpr int LDA_S = 36;
    constexpr int LDB_S = TB ? 36 : (BN_ + 8);
    constexpr int ASZ = 128 * LDA_S;
    constexpr int BSZ = TB ? (BN_ * 36) : (32 * (BN_ + 8));
    constexpr int STG = ASZ + BSZ;

    int z = blockIdx.z;
    int i2 = z % d2; int zt = z / d2; int i1 = zt % d1; int i0 = zt / d1;
    const float* A = Ag + (long)i0*a0 + (long)i1*a1 + (long)i2*a2;
    const float* B = Bg + (long)i0*b0 + (long)i1*b1 + (long)i2*b2;
    float*       C = Cg + (long)i0*c0 + (long)i1*c1 + (long)i2*c2;

    int m0 = blockIdx.y * 128;
    int n0 = blockIdx.x * BN_;
    if (causal && n0 >= m0 + 128) return;
    int Kend = K;
    if (kclip && m0 + 128 < Kend) Kend = m0 + 128;
    int nIt = Kend >> 5;

    int tid = threadIdx.x;
    int lane = tid & 31, wid = tid >> 5;
    int wm = wid >> 2, wn = wid & 3;
    constexpr int WNW = BN_ / 4;
    constexpr int WNT = WNW / 8;
    int r = lane >> 2, cq = lane & 3;

    int kk4 = tid & 7, mr = tid >> 3;

    auto LOAD = [&](int kt, int st) {
        float* As = smem + st * STG;
        float* Bs = As + ASZ;
        int k0 = kt * 32;
        #pragma unroll
        for (int i = 0; i < 4; i++) {
            int m = mr + i * 32;
            cpa16(&As[m * LDA_S + kk4 * 4], A + (long)(m0 + m) * lda + k0 + kk4 * 4);
        }
        if (TB) {
            #pragma unroll
            for (int i = 0; i < BN_ / 32; i++) {
                int nn = mr + i * 32;
                cpa16(&Bs[nn * 36 + kk4 * 4], B + (long)(n0 + nn) * ldb + k0 + kk4 * 4);
            }
        } else {
            constexpr int NP4 = BN_ / 4;
            constexpr int KP  = 256 / NP4;
            int n4 = tid % NP4, kr = tid / NP4;
            #pragma unroll
            for (int i = 0; i < 32 / KP; i++) {
                int kk = kr + i * KP;
                cpa16(&Bs[kk * LDB_S + n4 * 4], B + (long)(k0 + kk) * ldb + n0 + n4 * 4);
            }
        }
    };

    float acc[4][WNT][4];
    #pragma unroll
    for (int a = 0; a < 4; a++)
        #pragma unroll
        for (int b = 0; b < WNT; b++)
            #pragma unroll
            for (int c = 0; c < 4; c++) acc[a][b][c] = 0.f;

    LOAD(0, 0); cpa_commit();
    if (nIt > 1) LOAD(1, 1);
    cpa_commit();

    for (int it = 0; it < nIt; ++it) {
        if (it < nIt - 1) asm volatile("cp.async.wait_group 1;" ::: "memory");
        else              asm volatile("cp.async.wait_group 0;" ::: "memory");
        __syncthreads();
        const float* As = smem + (it % 3) * STG;
        const float* Bs = As + ASZ;

        #pragma unroll
        for (int ks = 0; ks < 32; ks += 8) {
            uint32_t af[4][4], bf[WNT][2];
            #pragma unroll
            for (int mt = 0; mt < 4; mt++) {
                int mb = wm * 64 + mt * 16;
                af[mt][0] = __float_as_uint(As[(mb + r    ) * LDA_S + ks + cq    ]);
                af[mt][1] = __float_as_uint(As[(mb + r + 8) * LDA_S + ks + cq    ]);
                af[mt][2] = __float_as_uint(As[(mb + r    ) * LDA_S + ks + cq + 4]);
                af[mt][3] = __float_as_uint(As[(mb + r + 8) * LDA_S + ks + cq + 4]);
            }
            #pragma unroll
            for (int nt = 0; nt < WNT; nt++) {
                int nb = wn * WNW + nt * 8;
                if (TB) {
                    bf[nt][0] = __float_as_uint(Bs[(nb + r) * 36 + ks + cq    ]);
                    bf[nt][1] = __float_as_uint(Bs[(nb + r) * 36 + ks + cq + 4]);
                } else {
                    bf[nt][0] = __float_as_uint(Bs[(ks + cq    ) * LDB_S + nb + r]);
                    bf[nt][1] = __float_as_uint(Bs[(ks + cq + 4) * LDB_S + nb + r]);
                }
            }
            #pragma unroll
            for (int mt = 0; mt < 4; mt++)
                #pragma unroll
                for (int nt = 0; nt < WNT; nt++) {
                    asm volatile(
                        "mma.sync.aligned.m16n8k8.row.col.f32.tf32.tf32.f32 "
                        "{%0,%1,%2,%3}, {%4,%5,%6,%7}, {%8,%9}, {%0,%1,%2,%3};"
                        : "+f"(acc[mt][nt][0]), "+f"(acc[mt][nt][1]),
                          "+f"(acc[mt][nt][2]), "+f"(acc[mt][nt][3])
                        : "r"(af[mt][0]), "r"(af[mt][1]), "r"(af[mt][2]), "r"(af[mt][3]),
                          "r"(bf[nt][0]), "r"(bf[nt][1]));
                }
        }

        if (it + 2 < nIt) { LOAD(it + 2, (it + 2) % 3); cpa_commit(); }
    }

    // ---- epilogue ----
    #pragma unroll
    for (int mt = 0; mt < 4; mt++) {
        #pragma unroll
        for (int nt = 0; nt < WNT; nt++) {
            int gm = m0 + wm * 64 + mt * 16 + r;
            int gn = n0 + wn * WNW + nt * 8 + cq * 2;
            #pragma unroll
            for (int half = 0; half < 2; half++) {
                long idx = (long)(gm + half * 8) * ldc + gn;
                float v0 = alpha * acc[mt][nt][half * 2    ];
                float v1 = alpha * acc[mt][nt][half * 2 + 1];
                if (beta != 0.f) {
                    float2 old = *(float2*)(C + idx);
                    v0 += beta * old.x; v1 += beta * old.y;
                }
                if (CVTO) { v0 = cvtf(v0); v1 = cvtf(v1); }
                *(float2*)(C + idx) = make_float2(v0, v1);
            }
        }
    }
}

// ---------------- SIMT GEMM (tiny LoRA shapes) ----------------
#define BM 64
#define BN 64
#define BK 16
template<bool TB>
__global__ void gemm_kernel(const float* __restrict__ A, const float* __restrict__ B,
                            float* __restrict__ C, int M, int N, int K,
                            int lda, int ldb, int ldc,
                            float alpha, float beta, int docvt) {
    __shared__ float As[BK][BM + 1];
    __shared__ float Bs[BK][BN + 1];
    int tid = threadIdx.x;
    int tx = tid % 16, ty = tid / 16;
    int m0 = blockIdx.y * BM, n0 = blockIdx.x * BN;
    float acc[4][4] = {};
    for (int k0 = 0; k0 < K; k0 += BK) {
        {
            int kk = tid % 16; int mrel = tid / 16;
            #pragma unroll
            for (int i = 0; i < 4; i++) {
                int m = mrel + i * 16;
                int gm = m0 + m;
                As[kk][m] = (gm < M) ? A[(long)gm * lda + k0 + kk] : 0.f;
            }
        }
        if (!TB) {
            int n = tid % 64; int kk0 = tid / 64;
            #pragma unroll
            for (int i = 0; i < 4; i++) {
                int kk = kk0 + i * 4;
                int gn = n0 + n;
                Bs[kk][n] = (gn < N) ? B[(long)(k0 + kk) * ldb + gn] : 0.f;
            }
        } else {
            int kk = tid % 16; int nrel = tid / 16;
            #pragma unroll
            for (int i = 0; i < 4; i++) {
                int n = nrel + i * 16;
                int gn = n0 + n;
                Bs[kk][n] = (gn < N) ? B[(long)gn * ldb + k0 + kk] : 0.f;
            }
        }
        __syncthreads();
        #pragma unroll
        for (int kk = 0; kk < BK; kk++) {
            float ra[4], rb[4];
            #pragma unroll
            for (int i = 0; i < 4; i++) ra[i] = As[kk][ty + 16 * i];
            #pragma unroll
            for (int j = 0; j < 4; j++) rb[j] = Bs[kk][tx + 16 * j];
            #pragma unroll
            for (int i = 0; i < 4; i++)
                #pragma unroll
                for (int j = 0; j < 4; j++)
                    acc[i][j] += ra[i] * rb[j];
        }
        __syncthreads();
    }
    #pragma unroll
    for (int i = 0; i < 4; i++) {
        int gm = m0 + ty + 16 * i;
        if (gm >= M) continue;
        #pragma unroll
        for (int j = 0; j < 4; j++) {
            int gn = n0 + tx + 16 * j;
            if (gn >= N) continue;
            long idx = (long)gm * ldc + gn;
            float prev = (beta != 0.f) ? beta * C[idx] : 0.f;
            float v = alpha * acc[i][j] + prev;
            C[idx] = docvt ? cvtf(v) : v;
        }
    }
}

// ---------------- host wrappers ----------------
static void sgemm(const float* A, const float* B, float* C,
                  int M, int N, int K, int lda, int ldb, int ldc,
                  float alpha, float beta, bool tb, int docvt) {
    dim3 grid((N + BN - 1) / BN, (M + BM - 1) / BM, 1);
    if (tb) gemm_kernel<true ><<<grid, 256>>>(A, B, C, M, N, K, lda, ldb, ldc, alpha, beta, docvt);
    else    gemm_kernel<false><<<grid, 256>>>(A, B, C, M, N, K, lda, ldb, ldc, alpha, beta, docvt);
}

struct BatchDesc {
    int nz = 1, d1 = 1, d2 = 1;
    long a0 = 0, a1 = 0, a2 = 0, b0 = 0, b1 = 0, b2 = 0, c0 = 0, c1 = 0, c2 = 0;
};

static int tc_smem_bytes(bool bn64, bool tb) {
    int ASZ = 128 * 36;
    int BSZ;
    if (bn64) BSZ = tb ? 64 * 36 : 32 * 72;
    else      BSZ = tb ? 128 * 36 : 32 * 136;
    return 3 * (ASZ + BSZ) * 4;
}

#define TG_LAUNCH(BNV, TBV, CVV)                                                         \
    do {                                                                                 \
        cudaFuncSetAttribute(tc_gemm_kernel<BNV, TBV, CVV>,                              \
                             cudaFuncAttributeMaxDynamicSharedMemorySize, smem);         \
        tc_gemm_kernel<BNV, TBV, CVV><<<grid, 256, smem>>>(A, B, C, M, N, K, lda, ldb,   \
            ldc, alpha, beta, bd.d1, bd.d2, bd.a0, bd.a1, bd.a2, bd.b0, bd.b1, bd.b2,    \
            bd.c0, bd.c1, bd.c2, causal, kclip);                                         \
    } while (0)

static void tgemm(const float* A, const float* B, float* C,
                  int M, int N, int K, int lda, int ldb, int ldc,
                  float alpha, float beta, bool tb, bool bn64, bool cvto,
                  const BatchDesc& bd = BatchDesc(), int causal = 0, int kclip = 0) {
    int bn = bn64 ? 64 : 128;
    dim3 grid((N + bn - 1) / bn, (M + 127) / 128, bd.nz);
    int smem = tc_smem_bytes(bn64, tb);
    if (!bn64) {
        if (tb) { if (cvto) TG_LAUNCH(128, true,  true); else TG_LAUNCH(128, true,  false); }
        else    { if (cvto) TG_LAUNCH(128, false, true); else TG_LAUNCH(128, false, false); }
    } else {
        if (tb) { if (cvto) TG_LAUNCH(64,  true,  true); else TG_LAUNCH(64,  true,  false); }
        else    { if (cvto) TG_LAUNCH(64,  false, true); else TG_LAUNCH(64,  false, false); }
    }
}

extern "C" void kernel_launch(void* const* d_in, const int* in_sizes, int n_in,
                              void* d_out, int out_size) {
    const int*   ids    = (const int*)  d_in[0];
    const float* emb    = (const float*)d_in[1];
    const float* Wq     = (const float*)d_in[2];
    const float* Wk     = (const float*)d_in[3];
    const float* Wv     = (const float*)d_in[4];
    const float* Wo     = (const float*)d_in[5];
    const float* W1     = (const float*)d_in[6];
    const float* W2     = (const float*)d_in[7];
    const float* ln1    = (const float*)d_in[8];
    const float* ln2    = (const float*)d_in[9];
    const float* lnf    = (const float*)d_in[10];
    const float* lmh    = (const float*)d_in[11];
    const float* Aq0    = (const float*)d_in[12];
    const float* Av0    = (const float*)d_in[14];
    const float* Bq     = (const float*)d_in[17];
    const float* Bv     = (const float*)d_in[19];
    float* out = (float*)d_out;

    float *x2, *h2, *qkv2, *o2, *u2, *p2, *t, *wcat, *woc, *w1c, *w2c, *lmc;
    cudaGetSymbolAddress((void**)&x2,   g_x2);
    cudaGetSymbolAddress((void**)&h2,   g_h2);
    cudaGetSymbolAddress((void**)&qkv2, g_qkv2);
    cudaGetSymbolAddress((void**)&o2,   g_o2);
    cudaGetSymbolAddress((void**)&u2,   g_u2);
    cudaGetSymbolAddress((void**)&p2,   g_p2);
    cudaGetSymbolAddress((void**)&t,    g_t);
    cudaGetSymbolAddress((void**)&wcat, g_wcat);
    cudaGetSymbolAddress((void**)&woc,  g_woc);
    cudaGetSymbolAddress((void**)&w1c,  g_w1c);
    cudaGetSymbolAddress((void**)&w2c,  g_w2c);
    cudaGetSymbolAddress((void**)&lmc,  g_lmc);

    float* x   = x2;            float* dx = x2 + (long)MM*DD;
    float* h   = h2;            float* dh = h2 + (long)MM*DD;
    float* p   = p2;            float* dp = p2 + (long)BB*HH*SS*SS;
    const long PRJ = (long)MM * 3*DD;         // pair stride in qkv2
    const long S2  = (long)SS * SS;
    const float scale = 1.f / 8.f;            // 1/sqrt(64)

    embed_kernel<<<(MM * DD) / 256, 256>>>(ids, emb, x, dx);
    cvtcopy_kernel<<<((long)DD * VV / 4) / 256, 256>>>(lmh, lmc);

    for (int l = 0; l < LL; l++) {
        const float* Aq0l = Aq0 + (long)l * RR * DD;
        const float* Av0l = Av0 + (long)l * RR * DD;
        const float* Bql  = Bq  + (long)l * DD * RR;
        const float* Bvl  = Bv  + (long)l * DD * RR;

        catw_kernel<<<(DD * DD) / 256, 256>>>(Wq + (long)l*DD*DD, Wk + (long)l*DD*DD,
                                              Wv + (long)l*DD*DD, wcat);
        cvtcopy_kernel<<<((long)DD * DD / 4) / 256, 256>>>(Wo + (long)l*DD*DD, woc);
        cvtcopy_kernel<<<((long)DD * FFD / 4) / 256, 256>>>(W1 + (long)l*DD*FFD, w1c);
        cvtcopy_kernel<<<((long)FFD * DD / 4) / 256, 256>>>(W2 + (long)l*FFD*DD, w2c);

        rms_jvp_kernel<<<MM, 256>>>(x, dx, ln1 + (long)l * DD, h, dh);

        // qkv projection (layer 0 tangent is exactly zero pre-LoRA)
        if (l == 0) {
            tgemm(h2, wcat, qkv2, MM, 3*DD, DD, DD, 3*DD, 3*DD, 1.f, 0.f, false, false, true);
            zero_kernel<<<((long)MM * 3*DD / 4) / 256, 256>>>(qkv2 + PRJ);
        } else {
            tgemm(h2, wcat, qkv2, 2*MM, 3*DD, DD, DD, 3*DD, 3*DD, 1.f, 0.f, false, false, true);
        }

        // LoRA tangent additions (tiny, SIMT)
        sgemm(h, Aq0l, t, MM, RR, DD, DD, DD, RR, 1.f, 0.f, true, 0);
        sgemm(t, Bql, qkv2 + PRJ,          MM, DD, RR, RR, RR, 3*DD, LORA_SCALE, 1.f, true, 1);
        sgemm(h, Av0l, t, MM, RR, DD, DD, DD, RR, 1.f, 0.f, true, 0);
        sgemm(t, Bvl, qkv2 + PRJ + 2*DD,   MM, DD, RR, RR, RR, 3*DD, LORA_SCALE, 1.f, true, 1);

        // scores: merged {p = q k^T, dp = dq k^T}; second pass dp += q dk^T (dk=0 at l=0)
        {
            BatchDesc bd; bd.nz = 2*BB*HH; bd.d1 = BB; bd.d2 = HH;
            bd.a0 = PRJ;  bd.a1 = (long)SS*3*DD; bd.a2 = HDD;
            bd.b0 = 0;    bd.b1 = (long)SS*3*DD; bd.b2 = HDD;
            bd.c0 = (long)BB*HH*S2; bd.c1 = (long)HH*S2; bd.c2 = S2;
            tgemm(qkv2, qkv2 + DD, p2, SS, SS, HDD, 3*DD, 3*DD, SS,
                  scale, 0.f, true, false, false, bd, 1, 0);
            if (l > 0) {
                BatchDesc b3 = bd; b3.nz = BB*HH; b3.a0 = 0; b3.b0 = 0; b3.c0 = 0;
                tgemm(qkv2, qkv2 + PRJ + DD, dp, SS, SS, HDD, 3*DD, 3*DD, SS,
                      scale, 1.f, true, false, false, b3, 1, 0);
            }
        }

        softmax_jvp_kernel<<<BB * HH * SS, 256>>>(p, dp);

        // PV: merged {o = p v, do = dp v} then do += p dv
        {
            BatchDesc bd; bd.nz = 2*BB*HH; bd.d1 = BB; bd.d2 = HH;
            bd.a0 = (long)BB*HH*S2; bd.a1 = (long)HH*S2; bd.a2 = S2;
            bd.b0 = 0;  bd.b1 = (long)SS*3*DD; bd.b2 = HDD;
            bd.c0 = (long)MM*DD; bd.c1 = (long)SS*DD; bd.c2 = HDD;
            tgemm(p2, qkv2 + 2*DD, o2, SS, HDD, SS, SS, 3*DD, DD,
                  1.f, 0.f, false, true, true, bd, 0, 1);
            BatchDesc b3 = bd; b3.nz = BB*HH; b3.a0 = 0; b3.b0 = 0; b3.c0 = 0;
            tgemm(p, qkv2 + PRJ + 2*DD, o2 + (long)MM*DD, SS, HDD, SS, SS, 3*DD, DD,
                  1.f, 1.f, false, true, true, b3, 0, 1);
        }

        // residual: x2 += o2 @ Wo (fused pair, M=4096) -- keep full precision out
        tgemm(o2, woc, x2, 2*MM, DD, DD, DD, DD, DD, 1.f, 1.f, false, false, false);

        // FFN
        rms_jvp_kernel<<<MM, 256>>>(x, dx, ln2 + (long)l * DD, h, dh);
        tgemm(h2, w1c, u2, 2*MM, FFD, DD, DD, FFD, FFD, 1.f, 0.f, false, false, false);
        gelu_jvp_kernel<<<(MM * FFD) / 256, 256>>>(u2, u2 + (long)MM*FFD);
        tgemm(u2, w2c, x2, 2*MM, DD, FFD, FFD, DD, DD, 1.f, 1.f, false, false, false);
    }

    // final norm + combine + lm head
    rms_jvp_kernel<<<MM, 256>>>(x, dx, lnf, h, dh);
    add_kernel<<<(MM * DD) / 256, 256>>>(h, dh);
    tgemm(h, lmc, out, MM, VV, DD, DD, VV, VV, 1.f, 0.f, false, false, false);
}